// round 14
// baseline (speedup 1.0000x reference)
#include <cuda_runtime.h>
#include <cuda_fp16.h>

#define BB  8
#define CC  128
#define CQK 16
#define NN  4096
#define TQ  128
#define TK  64
#define KT  (NN / TK)

typedef unsigned long long ull;
typedef unsigned int u32;

// f16 planes produced by qkv kernel (allocation-free scratch)
__device__ __half g_qh[BB * NN * CQK];
__device__ __half g_kh[BB * NN * CQK];
__device__ __half g_v [BB * CC * NN];   // [b][c][n], single plane

// ---------------- mma helpers (baseline PTX, sm_80+) ----------------
__device__ __forceinline__ u32 s2u(const void* p) {
    u32 a;
    asm("{ .reg .u64 t; cvta.to.shared.u64 t, %1; cvt.u32.u64 %0, t; }"
        : "=r"(a) : "l"(p));
    return a;
}
__device__ __forceinline__ void mma16816(float* d, const u32* a, u32 b0, u32 b1) {
    asm volatile(
        "mma.sync.aligned.m16n8k16.row.col.f32.f16.f16.f32 "
        "{%0,%1,%2,%3}, {%4,%5,%6,%7}, {%8,%9}, {%0,%1,%2,%3};"
        : "+f"(d[0]), "+f"(d[1]), "+f"(d[2]), "+f"(d[3])
        : "r"(a[0]), "r"(a[1]), "r"(a[2]), "r"(a[3]), "r"(b0), "r"(b1));
}
__device__ __forceinline__ void ldsm4(u32* r, u32 addr) {
    asm volatile("ldmatrix.sync.aligned.m8n8.x4.shared.b16 {%0,%1,%2,%3}, [%4];"
        : "=r"(r[0]), "=r"(r[1]), "=r"(r[2]), "=r"(r[3]) : "r"(addr));
}
__device__ __forceinline__ u32 ex2h2(u32 a) {
    u32 r;
    asm("ex2.approx.f16x2 %0, %1;" : "=r"(r) : "r"(a));
    return r;
}
__device__ __forceinline__ float nrm2h2(u32 a) {
    float2 f = __half22float2(*(__half2*)&a);
    return f.x * f.x + f.y * f.y;
}
#define CP16(dst, src) \
    asm volatile("cp.async.cg.shared.global [%0], [%1], 16;" :: "r"(dst), "l"(src))
#define CPCOMMIT() asm volatile("cp.async.commit_group;")
#define CPWAIT0()  asm volatile("cp.async.wait_group 0;")
#define CPWAIT1()  asm volatile("cp.async.wait_group 1;")
#define CPWAIT2()  asm volatile("cp.async.wait_group 2;")

// all-ones f16x2 B fragment for row-sum MMA (1.0h = 0x3C00)
#define ONESF 0x3C003C00u

#define LOG2E  1.44269504f
#define SH_A   3.6f
#define SH_B   1.0f
#define ACLAMP 15.9f

// ---------------------------------------------------------------------------
// Kernel 1: tensor-core QKV (unchanged from R13).
// ---------------------------------------------------------------------------
#define XS_PITCH32 68
#define WS_OFF 34816
#define QKV_SMEM (34816 + 160 * 136 * 2)

__global__ void __launch_bounds__(256, 1)
qkv_kernel(const float* __restrict__ x,
           const float* __restrict__ Wq,
           const float* __restrict__ Wk,
           const float* __restrict__ Wv) {
    extern __shared__ __align__(16) char sm[];
    __half* xs  = (__half*)sm;
    u32* xs32 = (u32*)sm;
    u32* ws32 = (u32*)(sm + WS_OFF);

    const int tid  = threadIdx.x;
    const int b    = blockIdx.y;
    const int n0   = blockIdx.x * 128;
    const int wid  = tid >> 5;
    const int lane = tid & 31;
    const int qr   = lane >> 2;
    const int qc   = lane & 3;

#pragma unroll
    for (int i = 0; i < 20; i++) {
        int idx4 = tid + i * 256;
        int row = idx4 >> 5, c4 = idx4 & 31;
        const float* src = (row < 16) ? (Wq + row * CC)
                         : (row < 32) ? (Wk + (row - 16) * CC)
                                      : (Wv + (row - 32) * CC);
        float4 v = *(const float4*)(src + c4 * 4);
        __half2 h01 = __floats2half2_rn(v.x, v.y);
        __half2 h23 = __floats2half2_rn(v.z, v.w);
        ws32[row * XS_PITCH32 + c4 * 2]     = *(u32*)&h01;
        ws32[row * XS_PITCH32 + c4 * 2 + 1] = *(u32*)&h23;
    }

    {
        int c2 = tid & 63, nh = tid >> 6;
        const float* px0 = x + ((ull)(b * CC + 2 * c2)) * NN + n0 + nh * 32;
        const float* px1 = px0 + NN;
#pragma unroll
        for (int j4 = 0; j4 < 8; j4++) {
            float4 r0 = *(const float4*)(px0 + j4 * 4);
            float4 r1 = *(const float4*)(px1 + j4 * 4);
            __half2 h0 = __floats2half2_rn(r0.x, r1.x);
            __half2 h1 = __floats2half2_rn(r0.y, r1.y);
            __half2 h2 = __floats2half2_rn(r0.z, r1.z);
            __half2 h3 = __floats2half2_rn(r0.w, r1.w);
            int nb = nh * 32 + j4 * 4;
            xs32[(nb + 0) * XS_PITCH32 + c2] = *(u32*)&h0;
            xs32[(nb + 1) * XS_PITCH32 + c2] = *(u32*)&h1;
            xs32[(nb + 2) * XS_PITCH32 + c2] = *(u32*)&h2;
            xs32[(nb + 3) * XS_PITCH32 + c2] = *(u32*)&h3;
        }
    }
    __syncthreads();

    float d[20][4];
#pragma unroll
    for (int cb = 0; cb < 20; cb++)
#pragma unroll
        for (int i = 0; i < 4; i++) d[cb][i] = 0.0f;

#pragma unroll
    for (int ks = 0; ks < 8; ks++) {
        u32 a[4];
        int ab = (wid * 16 + qr) * XS_PITCH32 + ks * 8 + qc;
        a[0] = xs32[ab];
        a[1] = xs32[ab + 8 * XS_PITCH32];
        a[2] = xs32[ab + 4];
        a[3] = xs32[ab + 8 * XS_PITCH32 + 4];
#pragma unroll
        for (int cb = 0; cb < 20; cb++) {
            int bb = (cb * 8 + qr) * XS_PITCH32 + ks * 8 + qc;
            mma16816(d[cb], a, ws32[bb], ws32[bb + 4]);
        }
    }

    {
        int n = n0 + wid * 16 + qr;
#pragma unroll
        for (int cb = 0; cb < 4; cb++) {
            u32* plane = (u32*)((cb < 2) ? g_qh : g_kh);
            int cidx = (cb & 1) * 4 + qc;
            __half2 h01 = __floats2half2_rn(d[cb][0], d[cb][1]);
            __half2 h23 = __floats2half2_rn(d[cb][2], d[cb][3]);
            plane[((ull)(b * NN + n)) * 8 + cidx]     = *(u32*)&h01;
            plane[((ull)(b * NN + n + 8)) * 8 + cidx] = *(u32*)&h23;
        }
    }

    __syncthreads();
#pragma unroll
    for (int cb = 4; cb < 20; cb++) {
        int ch = (cb - 4) * 8 + 2 * qc;
        int nn = wid * 16 + qr;
        xs[ch * 136 + nn]           = __float2half_rn(d[cb][0]);
        xs[(ch + 1) * 136 + nn]     = __float2half_rn(d[cb][1]);
        xs[ch * 136 + nn + 8]       = __float2half_rn(d[cb][2]);
        xs[(ch + 1) * 136 + nn + 8] = __float2half_rn(d[cb][3]);
    }
    __syncthreads();
    {
        u32* gv = (u32*)g_v;
#pragma unroll
        for (int i = 0; i < 32; i++) {
            int idx = tid + i * 256;
            int chr = idx >> 6, nw = idx & 63;
            gv[((ull)(b * CC + chr)) * (NN / 2) + (n0 >> 1) + nw] =
                xs32[chr * XS_PITCH32 + nw];
        }
    }
}

// ---------------------------------------------------------------------------
// Kernel 2: f16 flash attention, analytic shift, SOFTWARE-PIPELINED:
// QK(kt+1)+exp(kt+1) interleaved inside PV(kt)'s kb loop (K(kt+1) already
// resident: 3-stage ring + CPWAIT1 guarantees it before the per-kt sync).
// ---------------------------------------------------------------------------
#define QS  0u
#define KS(st) (4096u + (st) * 3072u)
#define VS(st) (13312u + (st) * 16384u)
#define SMEM_TOTAL 62464

#define ISSUE_KV(kt_, st_)                                                      \
    do {                                                                        \
        const int col0_ = (kt_) * TK;                                           \
        {                                                                       \
            int j_ = tid >> 1, w_ = tid & 1;                                    \
            const __half* src_ = g_kh                                           \
                + (ull)(b * NN + col0_ + j_) * CQK + w_ * 8;                    \
            CP16(smb + KS(st_) + j_ * 48 + w_ * 16, src_);                      \
        }                                                                       \
        _Pragma("unroll")                                                       \
        for (int i_ = 0; i_ < 8; i_++) {                                        \
            int e_ = tid + i_ * 128;                                            \
            int c_ = e_ >> 3, u_ = e_ & 7;                                      \
            const __half* src_ = g_v + (ull)(b * CC + c_) * NN + col0_ + u_ * 8;\
            CP16(smb + VS(st_) + c_ * 128 + ((u_ ^ (c_ & 7)) << 4), src_);      \
        }                                                                       \
        CPCOMMIT();                                                             \
    } while (0)

#define QK_MMA(qh_, s_, stg_)                                                   \
    do {                                                                        \
        _Pragma("unroll")                                                       \
        for (int nb = 0; nb < 8; nb++) {                                        \
            u32 base_ = KS(stg_) + (nb * 8 + qr) * 48 + qc * 4;                 \
            u32 bh0 = *(const u32*)(sm + base_);                                \
            u32 bh1 = *(const u32*)(sm + base_ + 16);                           \
            s_[nb][0] = s_[nb][1] = s_[nb][2] = s_[nb][3] = 0.0f;               \
            mma16816(s_[nb], qh_, bh0, bh1);                                    \
        }                                                                       \
    } while (0)

#define EXP_BLK(s_, ap_, cm0_, cm1_)                                            \
    do {                                                                        \
        _Pragma("unroll")                                                       \
        for (int nb = 0; nb < 8; nb++) {                                        \
            float a0 = fminf(fmaf(s_[nb][0], LOG2E, cm0_), ACLAMP);             \
            float a1 = fminf(fmaf(s_[nb][1], LOG2E, cm0_), ACLAMP);             \
            float a2 = fminf(fmaf(s_[nb][2], LOG2E, cm1_), ACLAMP);             \
            float a3 = fminf(fmaf(s_[nb][3], LOG2E, cm1_), ACLAMP);             \
            __half2 h01 = __floats2half2_rn(a0, a1);                            \
            __half2 h23 = __floats2half2_rn(a2, a3);                            \
            ap_[nb * 2 + 0] = ex2h2(*(u32*)&h01);                               \
            ap_[nb * 2 + 1] = ex2h2(*(u32*)&h23);                               \
        }                                                                       \
    } while (0)

// one kb step of the fused PV (both 16-row blocks share each V ldsm4)
#define PV_KB(kb_)                                                              \
    do {                                                                        \
        const u32* a0_ = apc0 + 4 * (kb_);                                      \
        const u32* a1_ = apc1 + 4 * (kb_);                                      \
        const int swz_ = (((2 * (kb_) + ubit) ^ (lane & 7)) << 4);              \
        mma16816(lpA, a0_, ONESF, ONESF);                                       \
        mma16816(lpB, a1_, ONESF, ONESF);                                       \
        _Pragma("unroll")                                                       \
        for (int g = 0; g < 8; g++) {                                           \
            u32 vv[4];                                                          \
            ldsm4(vv, smb + VS(st) + (u32)((g * 16 + crow) * 128) + swz_);      \
            mma16816(d0[2 * g + 0], a0_, vv[0], vv[1]);                         \
            mma16816(d0[2 * g + 1], a0_, vv[2], vv[3]);                         \
            mma16816(d1[2 * g + 0], a1_, vv[0], vv[1]);                         \
            mma16816(d1[2 * g + 1], a1_, vv[2], vv[3]);                         \
        }                                                                       \
    } while (0)

__global__ void __launch_bounds__(128, 2)
attn_kernel(const float* __restrict__ x,
            const float* __restrict__ gamma,
            float* __restrict__ out) {
    extern __shared__ __align__(128) char sm[];
    const u32 smb = s2u(sm);

    const int tid  = threadIdx.x;
    const int wid  = tid >> 5;
    const int lane = tid & 31;
    const int b    = blockIdx.y;
    const int row0 = blockIdx.x * TQ;
    const int qr   = lane >> 2;
    const int qc   = lane & 3;
    const int crow = ((lane >> 4) << 3) + (lane & 7);
    const int ubit = (lane >> 3) & 1;

    // ---- prologue: Q + K/V for kt 0,1,2 ----
    {
#pragma unroll
        for (int i = 0; i < 2; i++) {
            int e = tid + i * 128;
            int r = e >> 1, w = e & 1;
            const __half* src = g_qh + (ull)(b * NN + row0 + r) * CQK + w * 8;
            CP16(smb + QS + r * 32 + w * 16, src);
        }
        CPCOMMIT();
        ISSUE_KV(0, 0);
        ISSUE_KV(1, 1);
        ISSUE_KV(2, 2);
    }

    float d0[16][4], d1[16][4];
#pragma unroll
    for (int nb = 0; nb < 16; nb++)
#pragma unroll
        for (int i = 0; i < 4; i++) { d0[nb][i] = 0.0f; d1[nb][i] = 0.0f; }
    float lpA[4] = {0.f, 0.f, 0.f, 0.f};
    float lpB[4] = {0.f, 0.f, 0.f, 0.f};

    u32 qh0[4], qh1[4];
    float cm00, cm01, cm10, cm11;
    u32 apc0[16], apc1[16];

    {
        CPWAIT2();   // Q group + KV(0) complete
        __syncthreads();
        u32 base = QS + (wid * 32 + qr) * 32 + qc * 4;
        qh0[0] = *(const u32*)(sm + base);
        qh0[1] = *(const u32*)(sm + base + 8 * 32);
        qh0[2] = *(const u32*)(sm + base + 16);
        qh0[3] = *(const u32*)(sm + base + 8 * 32 + 16);
        base += 16 * 32;
        qh1[0] = *(const u32*)(sm + base);
        qh1[1] = *(const u32*)(sm + base + 8 * 32);
        qh1[2] = *(const u32*)(sm + base + 16);
        qh1[3] = *(const u32*)(sm + base + 8 * 32 + 16);

        float n00 = nrm2h2(qh0[0]) + nrm2h2(qh0[2]);
        float n01 = nrm2h2(qh0[1]) + nrm2h2(qh0[3]);
        float n10 = nrm2h2(qh1[0]) + nrm2h2(qh1[2]);
        float n11 = nrm2h2(qh1[1]) + nrm2h2(qh1[3]);
        n00 += __shfl_xor_sync(0xffffffffu, n00, 1);
        n00 += __shfl_xor_sync(0xffffffffu, n00, 2);
        n01 += __shfl_xor_sync(0xffffffffu, n01, 1);
        n01 += __shfl_xor_sync(0xffffffffu, n01, 2);
        n10 += __shfl_xor_sync(0xffffffffu, n10, 1);
        n10 += __shfl_xor_sync(0xffffffffu, n10, 2);
        n11 += __shfl_xor_sync(0xffffffffu, n11, 1);
        n11 += __shfl_xor_sync(0xffffffffu, n11, 2);
        cm00 = -(SH_A * sqrtf(n00) + SH_B) * LOG2E;
        cm01 = -(SH_A * sqrtf(n01) + SH_B) * LOG2E;
        cm10 = -(SH_A * sqrtf(n10) + SH_B) * LOG2E;
        cm11 = -(SH_A * sqrtf(n11) + SH_B) * LOG2E;

        // softmax for kt=0 (stage 0)
        float s[8][4];
        QK_MMA(qh0, s, 0);
        EXP_BLK(s, apc0, cm00, cm01);
        QK_MMA(qh1, s, 0);
        EXP_BLK(s, apc1, cm10, cm11);
    }

    for (int kt = 0; kt < KT; kt++) {
        const int st  = kt % 3;
        const int stn = (kt + 1) % 3;

        CPWAIT1();          // KV(kt+1) complete
        __syncthreads();
        if (kt >= 1 && kt + 2 < KT) {
            ISSUE_KV(kt + 2, (kt + 2) % 3);
        }
        const bool more = (kt + 1 < KT);

        float s[8][4];
        u32 apn0[16], apn1[16];

        // interleave next-tile softmax with current-tile PV
        if (more) QK_MMA(qh0, s, stn);
        PV_KB(0);
        if (more) EXP_BLK(s, apn0, cm00, cm01);
        PV_KB(1);
        if (more) QK_MMA(qh1, s, stn);
        PV_KB(2);
        if (more) EXP_BLK(s, apn1, cm10, cm11);
        PV_KB(3);

        if (more) {
#pragma unroll
            for (int i = 0; i < 16; i++) { apc0[i] = apn0[i]; apc1[i] = apn1[i]; }
        }
    }

    // ---- epilogue: normalize (lp exact from ones-MMA), fused residual ----
    const float g = gamma[0];
    const float li00 = g / lpA[0], li01 = g / lpA[2];
    const float li10 = g / lpB[0], li11 = g / lpB[2];

    {
        const int n = row0 + wid * 32 + qr;
#pragma unroll
        for (int nb = 0; nb < 16; nb++) {
            int c = nb * 8 + 2 * qc;
            ull i0 = ((ull)(b * CC + c)) * NN + n;
            out[i0]     = x[i0]     + d0[nb][0] * li00;
            out[i0 + 8] = x[i0 + 8] + d0[nb][2] * li01;
            ull i1 = i0 + NN;
            out[i1]     = x[i1]     + d0[nb][1] * li00;
            out[i1 + 8] = x[i1 + 8] + d0[nb][3] * li01;
            ull j0 = i0 + 16;
            out[j0]     = x[j0]     + d1[nb][0] * li10;
            out[j0 + 8] = x[j0 + 8] + d1[nb][2] * li11;
            ull j1 = j0 + NN;
            out[j1]     = x[j1]     + d1[nb][1] * li10;
            out[j1 + 8] = x[j1 + 8] + d1[nb][3] * li11;
        }
    }
}

// ---------------------------------------------------------------------------
extern "C" void kernel_launch(void* const* d_in, const int* in_sizes, int n_in,
                              void* d_out, int out_size) {
    const float* x     = (const float*)d_in[0];
    const float* Wq    = (const float*)d_in[1];
    const float* Wk    = (const float*)d_in[2];
    const float* Wv    = (const float*)d_in[3];
    const float* gamma = (const float*)d_in[4];
    float* out = (float*)d_out;

    cudaFuncSetAttribute(qkv_kernel,
                         cudaFuncAttributeMaxDynamicSharedMemorySize, QKV_SMEM);
    qkv_kernel<<<dim3(32, 8), 256, QKV_SMEM>>>(x, Wq, Wk, Wv);

    cudaFuncSetAttribute(attn_kernel,
                         cudaFuncAttributeMaxDynamicSharedMemorySize, SMEM_TOTAL);
    attn_kernel<<<dim3(32, 8), 128, SMEM_TOTAL>>>(x, gamma, out);
}

// round 16
// speedup vs baseline: 1.1652x; 1.1652x over previous
#include <cuda_runtime.h>
#include <cuda_fp16.h>

#define BB  8
#define CC  128
#define CQK 16
#define NN  4096
#define TQ  64
#define TK  64
#define KT  (NN / TK)

typedef unsigned long long ull;
typedef unsigned int u32;

// f16 planes produced by qkv kernel (allocation-free scratch)
__device__ __half g_qh[BB * NN * CQK];
__device__ __half g_kh[BB * NN * CQK];
__device__ __half g_v [BB * CC * NN];   // [b][c][n], single plane

// ---------------- mma helpers (baseline PTX, sm_80+) ----------------
__device__ __forceinline__ u32 s2u(const void* p) {
    u32 a;
    asm("{ .reg .u64 t; cvta.to.shared.u64 t, %1; cvt.u32.u64 %0, t; }"
        : "=r"(a) : "l"(p));
    return a;
}
__device__ __forceinline__ void mma16816(float* d, const u32* a, u32 b0, u32 b1) {
    asm volatile(
        "mma.sync.aligned.m16n8k16.row.col.f32.f16.f16.f32 "
        "{%0,%1,%2,%3}, {%4,%5,%6,%7}, {%8,%9}, {%0,%1,%2,%3};"
        : "+f"(d[0]), "+f"(d[1]), "+f"(d[2]), "+f"(d[3])
        : "r"(a[0]), "r"(a[1]), "r"(a[2]), "r"(a[3]), "r"(b0), "r"(b1));
}
__device__ __forceinline__ void ldsm4(u32* r, u32 addr) {
    asm volatile("ldmatrix.sync.aligned.m8n8.x4.shared.b16 {%0,%1,%2,%3}, [%4];"
        : "=r"(r[0]), "=r"(r[1]), "=r"(r[2]), "=r"(r[3]) : "r"(addr));
}
__device__ __forceinline__ u32 ex2h2(u32 a) {
    u32 r;
    asm("ex2.approx.f16x2 %0, %1;" : "=r"(r) : "r"(a));
    return r;
}
__device__ __forceinline__ float nrm2h2(u32 a) {
    float2 f = __half22float2(*(__half2*)&a);
    return f.x * f.x + f.y * f.y;
}
#define CP16(dst, src) \
    asm volatile("cp.async.cg.shared.global [%0], [%1], 16;" :: "r"(dst), "l"(src))
#define CPCOMMIT() asm volatile("cp.async.commit_group;")
#define CPWAIT0()  asm volatile("cp.async.wait_group 0;")
#define CPWAIT1()  asm volatile("cp.async.wait_group 1;")
#define CPWAIT3()  asm volatile("cp.async.wait_group 3;")

// all-ones f16x2 B fragment for row-sum MMA (1.0h = 0x3C00)
#define ONESF 0x3C003C00u

#define LOG2E  1.44269504f
#define SH_A   3.6f
#define SH_B   1.0f
#define ACLAMP 15.9f

// ---------------------------------------------------------------------------
// Kernel 1: tensor-core QKV (unchanged from R13 best).
// ---------------------------------------------------------------------------
#define XS_PITCH32 68
#define WS_OFF 34816
#define QKV_SMEM (34816 + 160 * 136 * 2)

__global__ void __launch_bounds__(256, 1)
qkv_kernel(const float* __restrict__ x,
           const float* __restrict__ Wq,
           const float* __restrict__ Wk,
           const float* __restrict__ Wv) {
    extern __shared__ __align__(16) char sm[];
    __half* xs  = (__half*)sm;
    u32* xs32 = (u32*)sm;
    u32* ws32 = (u32*)(sm + WS_OFF);

    const int tid  = threadIdx.x;
    const int b    = blockIdx.y;
    const int n0   = blockIdx.x * 128;
    const int wid  = tid >> 5;
    const int lane = tid & 31;
    const int qr   = lane >> 2;
    const int qc   = lane & 3;

#pragma unroll
    for (int i = 0; i < 20; i++) {
        int idx4 = tid + i * 256;
        int row = idx4 >> 5, c4 = idx4 & 31;
        const float* src = (row < 16) ? (Wq + row * CC)
                         : (row < 32) ? (Wk + (row - 16) * CC)
                                      : (Wv + (row - 32) * CC);
        float4 v = *(const float4*)(src + c4 * 4);
        __half2 h01 = __floats2half2_rn(v.x, v.y);
        __half2 h23 = __floats2half2_rn(v.z, v.w);
        ws32[row * XS_PITCH32 + c4 * 2]     = *(u32*)&h01;
        ws32[row * XS_PITCH32 + c4 * 2 + 1] = *(u32*)&h23;
    }

    {
        int c2 = tid & 63, nh = tid >> 6;
        const float* px0 = x + ((ull)(b * CC + 2 * c2)) * NN + n0 + nh * 32;
        const float* px1 = px0 + NN;
#pragma unroll
        for (int j4 = 0; j4 < 8; j4++) {
            float4 r0 = *(const float4*)(px0 + j4 * 4);
            float4 r1 = *(const float4*)(px1 + j4 * 4);
            __half2 h0 = __floats2half2_rn(r0.x, r1.x);
            __half2 h1 = __floats2half2_rn(r0.y, r1.y);
            __half2 h2 = __floats2half2_rn(r0.z, r1.z);
            __half2 h3 = __floats2half2_rn(r0.w, r1.w);
            int nb = nh * 32 + j4 * 4;
            xs32[(nb + 0) * XS_PITCH32 + c2] = *(u32*)&h0;
            xs32[(nb + 1) * XS_PITCH32 + c2] = *(u32*)&h1;
            xs32[(nb + 2) * XS_PITCH32 + c2] = *(u32*)&h2;
            xs32[(nb + 3) * XS_PITCH32 + c2] = *(u32*)&h3;
        }
    }
    __syncthreads();

    float d[20][4];
#pragma unroll
    for (int cb = 0; cb < 20; cb++)
#pragma unroll
        for (int i = 0; i < 4; i++) d[cb][i] = 0.0f;

#pragma unroll
    for (int ks = 0; ks < 8; ks++) {
        u32 a[4];
        int ab = (wid * 16 + qr) * XS_PITCH32 + ks * 8 + qc;
        a[0] = xs32[ab];
        a[1] = xs32[ab + 8 * XS_PITCH32];
        a[2] = xs32[ab + 4];
        a[3] = xs32[ab + 8 * XS_PITCH32 + 4];
#pragma unroll
        for (int cb = 0; cb < 20; cb++) {
            int bb = (cb * 8 + qr) * XS_PITCH32 + ks * 8 + qc;
            mma16816(d[cb], a, ws32[bb], ws32[bb + 4]);
        }
    }

    {
        int n = n0 + wid * 16 + qr;
#pragma unroll
        for (int cb = 0; cb < 4; cb++) {
            u32* plane = (u32*)((cb < 2) ? g_qh : g_kh);
            int cidx = (cb & 1) * 4 + qc;
            __half2 h01 = __floats2half2_rn(d[cb][0], d[cb][1]);
            __half2 h23 = __floats2half2_rn(d[cb][2], d[cb][3]);
            plane[((ull)(b * NN + n)) * 8 + cidx]     = *(u32*)&h01;
            plane[((ull)(b * NN + n + 8)) * 8 + cidx] = *(u32*)&h23;
        }
    }

    __syncthreads();
#pragma unroll
    for (int cb = 4; cb < 20; cb++) {
        int ch = (cb - 4) * 8 + 2 * qc;
        int nn = wid * 16 + qr;
        xs[ch * 136 + nn]           = __float2half_rn(d[cb][0]);
        xs[(ch + 1) * 136 + nn]     = __float2half_rn(d[cb][1]);
        xs[ch * 136 + nn + 8]       = __float2half_rn(d[cb][2]);
        xs[(ch + 1) * 136 + nn + 8] = __float2half_rn(d[cb][3]);
    }
    __syncthreads();
    {
        u32* gv = (u32*)g_v;
#pragma unroll
        for (int i = 0; i < 32; i++) {
            int idx = tid + i * 256;
            int chr = idx >> 6, nw = idx & 63;
            gv[((ull)(b * CC + chr)) * (NN / 2) + (n0 >> 1) + nw] =
                xs32[chr * XS_PITCH32 + nw];
        }
    }
}

// ---------------------------------------------------------------------------
// Kernel 2: f16 flash attention, analytic per-row shift, R13 loop structure,
// 16 q-rows/warp (TQ=64, 128 thr) for 3 CTAs/SM occupancy.
// ---------------------------------------------------------------------------
#define QS  0u                                   // 64 rows x 32B = 2048
#define KS(st) (2048u + (st) * 3072u)            // 64 rows x 48B
#define VS(st) (11264u + (st) * 16384u)          // 128 ch x 128B swizzled
#define SMEM_TOTAL 60416

// K tile: 64 rows x 2 chunks = 128 cp.asyncs (exactly one per thread!)
#define ISSUE_KV(kt_, st_)                                                      \
    do {                                                                        \
        const int col0_ = (kt_) * TK;                                           \
        {                                                                       \
            int j_ = tid >> 1, w_ = tid & 1;                                    \
            const __half* src_ = g_kh                                           \
                + (ull)(b * NN + col0_ + j_) * CQK + w_ * 8;                    \
            CP16(smb + KS(st_) + j_ * 48 + w_ * 16, src_);                      \
        }                                                                       \
        _Pragma("unroll")                                                       \
        for (int i_ = 0; i_ < 8; i_++) {                                        \
            int e_ = tid + i_ * 128;                                            \
            int c_ = e_ >> 3, u_ = e_ & 7;                                      \
            const __half* src_ = g_v + (ull)(b * CC + c_) * NN + col0_ + u_ * 8;\
            CP16(smb + VS(st_) + c_ * 128 + ((u_ ^ (c_ & 7)) << 4), src_);      \
        }                                                                       \
        CPCOMMIT();                                                             \
    } while (0)

#define QK_SOFTMAX(qh_, ap_, cm0_, cm1_)                                        \
    do {                                                                        \
        float s_[8][4];                                                         \
        _Pragma("unroll")                                                       \
        for (int nb = 0; nb < 8; nb++) {                                        \
            u32 base_ = KS(st) + (nb * 8 + qr) * 48 + qc * 4;                   \
            u32 bh0 = *(const u32*)(sm + base_);                                \
            u32 bh1 = *(const u32*)(sm + base_ + 16);                           \
            s_[nb][0] = s_[nb][1] = s_[nb][2] = s_[nb][3] = 0.0f;               \
            mma16816(s_[nb], qh_, bh0, bh1);                                    \
        }                                                                       \
        _Pragma("unroll")                                                       \
        for (int nb = 0; nb < 8; nb++) {                                        \
            float a0 = fminf(fmaf(s_[nb][0], LOG2E, cm0_), ACLAMP);             \
            float a1 = fminf(fmaf(s_[nb][1], LOG2E, cm0_), ACLAMP);             \
            float a2 = fminf(fmaf(s_[nb][2], LOG2E, cm1_), ACLAMP);             \
            float a3 = fminf(fmaf(s_[nb][3], LOG2E, cm1_), ACLAMP);             \
            __half2 h01 = __floats2half2_rn(a0, a1);                            \
            __half2 h23 = __floats2half2_rn(a2, a3);                            \
            ap_[nb * 2 + 0] = ex2h2(*(u32*)&h01);                               \
            ap_[nb * 2 + 1] = ex2h2(*(u32*)&h23);                               \
        }                                                                       \
    } while (0)

__global__ void __launch_bounds__(128, 3)
attn_kernel(const float* __restrict__ x,
            const float* __restrict__ gamma,
            float* __restrict__ out) {
    extern __shared__ __align__(128) char sm[];
    const u32 smb = s2u(sm);

    const int tid  = threadIdx.x;
    const int wid  = tid >> 5;
    const int lane = tid & 31;
    const int b    = blockIdx.y;
    const int row0 = blockIdx.x * TQ;
    const int qr   = lane >> 2;
    const int qc   = lane & 3;

    // ---- prologue: Q + K/V for kt 0,1,2 ----
    {
        int r = tid >> 1, w = tid & 1;
        const __half* src = g_qh + (ull)(b * NN + row0 + r) * CQK + w * 8;
        CP16(smb + QS + r * 32 + w * 16, src);
        CPCOMMIT();
        ISSUE_KV(0, 0);
        ISSUE_KV(1, 1);
        ISSUE_KV(2, 2);
    }

    float d[16][4];
#pragma unroll
    for (int nb = 0; nb < 16; nb++)
#pragma unroll
        for (int i = 0; i < 4; i++) d[nb][i] = 0.0f;
    float lp[4] = {0.f, 0.f, 0.f, 0.f};

    u32 qh[4];
    float cm0, cm1;
    {
        CPWAIT3();   // Q group done
        __syncthreads();
        u32 base = QS + (wid * 16 + qr) * 32 + qc * 4;
        qh[0] = *(const u32*)(sm + base);
        qh[1] = *(const u32*)(sm + base + 8 * 32);
        qh[2] = *(const u32*)(sm + base + 16);
        qh[3] = *(const u32*)(sm + base + 8 * 32 + 16);

        float n0 = nrm2h2(qh[0]) + nrm2h2(qh[2]);
        float n1 = nrm2h2(qh[1]) + nrm2h2(qh[3]);
        n0 += __shfl_xor_sync(0xffffffffu, n0, 1);
        n0 += __shfl_xor_sync(0xffffffffu, n0, 2);
        n1 += __shfl_xor_sync(0xffffffffu, n1, 1);
        n1 += __shfl_xor_sync(0xffffffffu, n1, 2);
        cm0 = -(SH_A * sqrtf(n0) + SH_B) * LOG2E;
        cm1 = -(SH_A * sqrtf(n1) + SH_B) * LOG2E;
    }

    for (int kt = 0; kt < KT; kt++) {
        const int st = kt % 3;

        if (kt + 1 < KT) { CPWAIT1(); } else { CPWAIT0(); }
        __syncthreads();
        if (kt >= 1 && kt + 2 < KT) {
            ISSUE_KV(kt + 2, (kt + 2) % 3);
        }

        u32 ap[16];
        QK_SOFTMAX(qh, ap, cm0, cm1);

        const int crow = ((lane >> 4) << 3) + (lane & 7);
        const int ubit = (lane >> 3) & 1;
#pragma unroll
        for (int kb = 0; kb < 4; kb++) {
            const u32* a = ap + 4 * kb;
            const int swz = (((2 * kb + ubit) ^ (lane & 7)) << 4);
            mma16816(lp, a, ONESF, ONESF);
#pragma unroll
            for (int g = 0; g < 8; g++) {
                u32 vv[4];
                ldsm4(vv, smb + VS(st) + (u32)((g * 16 + crow) * 128) + swz);
                mma16816(d[2 * g + 0], a, vv[0], vv[1]);
                mma16816(d[2 * g + 1], a, vv[2], vv[3]);
            }
        }
    }

    // ---- epilogue: normalize (lp exact from ones-MMA), fused residual ----
    const float g = gamma[0];
    const float li0 = g / lp[0], li1 = g / lp[2];

    {
        const int n = row0 + wid * 16 + qr;
#pragma unroll
        for (int nb = 0; nb < 16; nb++) {
            int c = nb * 8 + 2 * qc;
            ull i0 = ((ull)(b * CC + c)) * NN + n;
            out[i0]     = x[i0]     + d[nb][0] * li0;
            out[i0 + 8] = x[i0 + 8] + d[nb][2] * li1;
            ull i1 = i0 + NN;
            out[i1]     = x[i1]     + d[nb][1] * li0;
            out[i1 + 8] = x[i1 + 8] + d[nb][3] * li1;
        }
    }
}

// ---------------------------------------------------------------------------
extern "C" void kernel_launch(void* const* d_in, const int* in_sizes, int n_in,
                              void* d_out, int out_size) {
    const float* x     = (const float*)d_in[0];
    const float* Wq    = (const float*)d_in[1];
    const float* Wk    = (const float*)d_in[2];
    const float* Wv    = (const float*)d_in[3];
    const float* gamma = (const float*)d_in[4];
    float* out = (float*)d_out;

    cudaFuncSetAttribute(qkv_kernel,
                         cudaFuncAttributeMaxDynamicSharedMemorySize, QKV_SMEM);
    qkv_kernel<<<dim3(32, 8), 256, QKV_SMEM>>>(x, Wq, Wk, Wv);

    cudaFuncSetAttribute(attn_kernel,
                         cudaFuncAttributeMaxDynamicSharedMemorySize, SMEM_TOTAL);
    attn_kernel<<<dim3(64, 8), 128, SMEM_TOTAL>>>(x, gamma, out);
}

// round 17
// speedup vs baseline: 1.3390x; 1.1491x over previous
#include <cuda_runtime.h>
#include <cuda_fp16.h>

#define BB  8
#define CC  128
#define CQK 16
#define NN  4096
#define TQ  128
#define TK  64
#define KT  (NN / TK)

typedef unsigned long long ull;
typedef unsigned int u32;

// f16 planes produced by qkv kernel (allocation-free scratch)
__device__ __half g_qh[BB * NN * CQK];
__device__ __half g_kh[BB * NN * CQK];
__device__ __half g_v [BB * CC * NN];   // [b][c][n], single plane

// ---------------- mma helpers (baseline PTX, sm_80+) ----------------
__device__ __forceinline__ u32 s2u(const void* p) {
    u32 a;
    asm("{ .reg .u64 t; cvta.to.shared.u64 t, %1; cvt.u32.u64 %0, t; }"
        : "=r"(a) : "l"(p));
    return a;
}
__device__ __forceinline__ void mma16816(float* d, const u32* a, u32 b0, u32 b1) {
    asm volatile(
        "mma.sync.aligned.m16n8k16.row.col.f32.f16.f16.f32 "
        "{%0,%1,%2,%3}, {%4,%5,%6,%7}, {%8,%9}, {%0,%1,%2,%3};"
        : "+f"(d[0]), "+f"(d[1]), "+f"(d[2]), "+f"(d[3])
        : "r"(a[0]), "r"(a[1]), "r"(a[2]), "r"(a[3]), "r"(b0), "r"(b1));
}
__device__ __forceinline__ void ldsm4(u32* r, u32 addr) {
    asm volatile("ldmatrix.sync.aligned.m8n8.x4.shared.b16 {%0,%1,%2,%3}, [%4];"
        : "=r"(r[0]), "=r"(r[1]), "=r"(r[2]), "=r"(r[3]) : "r"(addr));
}
__device__ __forceinline__ u32 ex2h2(u32 a) {
    u32 r;
    asm("ex2.approx.f16x2 %0, %1;" : "=r"(r) : "r"(a));
    return r;
}
__device__ __forceinline__ float nrm2h2(u32 a) {
    float2 f = __half22float2(*(__half2*)&a);
    return f.x * f.x + f.y * f.y;
}
#define CP16(dst, src) \
    asm volatile("cp.async.cg.shared.global [%0], [%1], 16;" :: "r"(dst), "l"(src))
#define CPCOMMIT() asm volatile("cp.async.commit_group;")
#define CPWAIT0()  asm volatile("cp.async.wait_group 0;")
#define CPWAIT2()  asm volatile("cp.async.wait_group 2;")

// all-ones f16x2 B fragment for row-sum MMA (1.0h = 0x3C00)
#define ONESF 0x3C003C00u

#define LOG2E  1.44269504f
#define SH_A   3.6f
#define SH_B   1.0f
#define ACLAMP 15.9f

// ---------------------------------------------------------------------------
// Kernel 1: tensor-core QKV (R13 logic; 2 CTAs/SM for single-wave execution).
// ---------------------------------------------------------------------------
#define XS_PITCH32 68
#define WS_OFF 34816
#define QKV_SMEM (34816 + 160 * 136 * 2)

__global__ void __launch_bounds__(256, 2)
qkv_kernel(const float* __restrict__ x,
           const float* __restrict__ Wq,
           const float* __restrict__ Wk,
           const float* __restrict__ Wv) {
    extern __shared__ __align__(16) char sm[];
    __half* xs  = (__half*)sm;
    u32* xs32 = (u32*)sm;
    u32* ws32 = (u32*)(sm + WS_OFF);

    const int tid  = threadIdx.x;
    const int b    = blockIdx.y;
    const int n0   = blockIdx.x * 128;
    const int wid  = tid >> 5;
    const int lane = tid & 31;
    const int qr   = lane >> 2;
    const int qc   = lane & 3;

#pragma unroll
    for (int i = 0; i < 20; i++) {
        int idx4 = tid + i * 256;
        int row = idx4 >> 5, c4 = idx4 & 31;
        const float* src = (row < 16) ? (Wq + row * CC)
                         : (row < 32) ? (Wk + (row - 16) * CC)
                                      : (Wv + (row - 32) * CC);
        float4 v = *(const float4*)(src + c4 * 4);
        __half2 h01 = __floats2half2_rn(v.x, v.y);
        __half2 h23 = __floats2half2_rn(v.z, v.w);
        ws32[row * XS_PITCH32 + c4 * 2]     = *(u32*)&h01;
        ws32[row * XS_PITCH32 + c4 * 2 + 1] = *(u32*)&h23;
    }

    {
        int c2 = tid & 63, nh = tid >> 6;
        const float* px0 = x + ((ull)(b * CC + 2 * c2)) * NN + n0 + nh * 32;
        const float* px1 = px0 + NN;
#pragma unroll
        for (int j4 = 0; j4 < 8; j4++) {
            float4 r0 = *(const float4*)(px0 + j4 * 4);
            float4 r1 = *(const float4*)(px1 + j4 * 4);
            __half2 h0 = __floats2half2_rn(r0.x, r1.x);
            __half2 h1 = __floats2half2_rn(r0.y, r1.y);
            __half2 h2 = __floats2half2_rn(r0.z, r1.z);
            __half2 h3 = __floats2half2_rn(r0.w, r1.w);
            int nb = nh * 32 + j4 * 4;
            xs32[(nb + 0) * XS_PITCH32 + c2] = *(u32*)&h0;
            xs32[(nb + 1) * XS_PITCH32 + c2] = *(u32*)&h1;
            xs32[(nb + 2) * XS_PITCH32 + c2] = *(u32*)&h2;
            xs32[(nb + 3) * XS_PITCH32 + c2] = *(u32*)&h3;
        }
    }
    __syncthreads();

    float d[20][4];
#pragma unroll
    for (int cb = 0; cb < 20; cb++)
#pragma unroll
        for (int i = 0; i < 4; i++) d[cb][i] = 0.0f;

#pragma unroll
    for (int ks = 0; ks < 8; ks++) {
        u32 a[4];
        int ab = (wid * 16 + qr) * XS_PITCH32 + ks * 8 + qc;
        a[0] = xs32[ab];
        a[1] = xs32[ab + 8 * XS_PITCH32];
        a[2] = xs32[ab + 4];
        a[3] = xs32[ab + 8 * XS_PITCH32 + 4];
#pragma unroll
        for (int cb = 0; cb < 20; cb++) {
            int bb = (cb * 8 + qr) * XS_PITCH32 + ks * 8 + qc;
            mma16816(d[cb], a, ws32[bb], ws32[bb + 4]);
        }
    }

    {
        int n = n0 + wid * 16 + qr;
#pragma unroll
        for (int cb = 0; cb < 4; cb++) {
            u32* plane = (u32*)((cb < 2) ? g_qh : g_kh);
            int cidx = (cb & 1) * 4 + qc;
            __half2 h01 = __floats2half2_rn(d[cb][0], d[cb][1]);
            __half2 h23 = __floats2half2_rn(d[cb][2], d[cb][3]);
            plane[((ull)(b * NN + n)) * 8 + cidx]     = *(u32*)&h01;
            plane[((ull)(b * NN + n + 8)) * 8 + cidx] = *(u32*)&h23;
        }
    }

    __syncthreads();
#pragma unroll
    for (int cb = 4; cb < 20; cb++) {
        int ch = (cb - 4) * 8 + 2 * qc;
        int nn = wid * 16 + qr;
        xs[ch * 136 + nn]           = __float2half_rn(d[cb][0]);
        xs[(ch + 1) * 136 + nn]     = __float2half_rn(d[cb][1]);
        xs[ch * 136 + nn + 8]       = __float2half_rn(d[cb][2]);
        xs[(ch + 1) * 136 + nn + 8] = __float2half_rn(d[cb][3]);
    }
    __syncthreads();
    {
        u32* gv = (u32*)g_v;
#pragma unroll
        for (int i = 0; i < 32; i++) {
            int idx = tid + i * 256;
            int chr = idx >> 6, nw = idx & 63;
            gv[((ull)(b * CC + chr)) * (NN / 2) + (n0 >> 1) + nw] =
                xs32[chr * XS_PITCH32 + nw];
        }
    }
}

// ---------------------------------------------------------------------------
// Kernel 2: f16 flash attention, analytic per-row shift, 32 q-rows/warp
// (R13 geometry), 4-stage K/V ring with ONE barrier per 2 tiles:
//   barrier at even kt after wait_group 0 => tiles kt, kt+1 complete+visible;
//   writes at odd positions go to stage (kt+3)%4, disjoint from any stage
//   readable within the <=1-tile warp skew window.
// ---------------------------------------------------------------------------
#define QS  0u                                   // 128 rows x 32B = 4096
#define KS(st) (4096u + (st) * 3072u)            // 64 rows x 48B
#define VS(st) (16384u + (st) * 16384u)          // 128 ch x 128B swizzled
#define SMEM_TOTAL 81920

#define ISSUE_KV(kt_, st_)                                                      \
    do {                                                                        \
        const int col0_ = (kt_) * TK;                                           \
        {                                                                       \
            int j_ = tid >> 1, w_ = tid & 1;                                    \
            const __half* src_ = g_kh                                           \
                + (ull)(b * NN + col0_ + j_) * CQK + w_ * 8;                    \
            CP16(smb + KS(st_) + j_ * 48 + w_ * 16, src_);                      \
        }                                                                       \
        _Pragma("unroll")                                                       \
        for (int i_ = 0; i_ < 8; i_++) {                                        \
            int e_ = tid + i_ * 128;                                            \
            int c_ = e_ >> 3, u_ = e_ & 7;                                      \
            const __half* src_ = g_v + (ull)(b * CC + c_) * NN + col0_ + u_ * 8;\
            CP16(smb + VS(st_) + c_ * 128 + ((u_ ^ (c_ & 7)) << 4), src_);      \
        }                                                                       \
        CPCOMMIT();                                                             \
    } while (0)

#define QK_SOFTMAX(qh_, ap_, cm0_, cm1_, st_)                                   \
    do {                                                                        \
        float s_[8][4];                                                         \
        _Pragma("unroll")                                                       \
        for (int nb = 0; nb < 8; nb++) {                                        \
            u32 base_ = KS(st_) + (nb * 8 + qr) * 48 + qc * 4;                  \
            u32 bh0 = *(const u32*)(sm + base_);                                \
            u32 bh1 = *(const u32*)(sm + base_ + 16);                           \
            s_[nb][0] = s_[nb][1] = s_[nb][2] = s_[nb][3] = 0.0f;               \
            mma16816(s_[nb], qh_, bh0, bh1);                                    \
        }                                                                       \
        _Pragma("unroll")                                                       \
        for (int nb = 0; nb < 8; nb++) {                                        \
            float a0 = fminf(fmaf(s_[nb][0], LOG2E, cm0_), ACLAMP);             \
            float a1 = fminf(fmaf(s_[nb][1], LOG2E, cm0_), ACLAMP);             \
            float a2 = fminf(fmaf(s_[nb][2], LOG2E, cm1_), ACLAMP);             \
            float a3 = fminf(fmaf(s_[nb][3], LOG2E, cm1_), ACLAMP);             \
            __half2 h01 = __floats2half2_rn(a0, a1);                            \
            __half2 h23 = __floats2half2_rn(a2, a3);                            \
            ap_[nb * 2 + 0] = ex2h2(*(u32*)&h01);                               \
            ap_[nb * 2 + 1] = ex2h2(*(u32*)&h23);                               \
        }                                                                       \
    } while (0)

// full tile processing: both 16-row blocks, then fused PV
#define PROCESS(st_)                                                            \
    do {                                                                        \
        u32 ap0[16], ap1[16];                                                   \
        QK_SOFTMAX(qh0, ap0, cm00, cm01, st_);                                  \
        QK_SOFTMAX(qh1, ap1, cm10, cm11, st_);                                  \
        _Pragma("unroll")                                                       \
        for (int kb = 0; kb < 4; kb++) {                                        \
            const u32* a0 = ap0 + 4 * kb;                                       \
            const u32* a1 = ap1 + 4 * kb;                                       \
            const int swz = (((2 * kb + ubit) ^ (lane & 7)) << 4);              \
            mma16816(lpA, a0, ONESF, ONESF);                                    \
            mma16816(lpB, a1, ONESF, ONESF);                                    \
            _Pragma("unroll")                                                   \
            for (int g = 0; g < 8; g++) {                                       \
                u32 vv[4];                                                      \
                ldsm4(vv, smb + VS(st_) + (u32)((g * 16 + crow) * 128) + swz);  \
                mma16816(d0[2 * g + 0], a0, vv[0], vv[1]);                      \
                mma16816(d0[2 * g + 1], a0, vv[2], vv[3]);                      \
                mma16816(d1[2 * g + 0], a1, vv[0], vv[1]);                      \
                mma16816(d1[2 * g + 1], a1, vv[2], vv[3]);                      \
            }                                                                   \
        }                                                                       \
    } while (0)

__global__ void __launch_bounds__(128, 2)
attn_kernel(const float* __restrict__ x,
            const float* __restrict__ gamma,
            float* __restrict__ out) {
    extern __shared__ __align__(128) char sm[];
    const u32 smb = s2u(sm);

    const int tid  = threadIdx.x;
    const int wid  = tid >> 5;
    const int lane = tid & 31;
    const int b    = blockIdx.y;
    const int row0 = blockIdx.x * TQ;
    const int qr   = lane >> 2;
    const int qc   = lane & 3;
    const int crow = ((lane >> 4) << 3) + (lane & 7);
    const int ubit = (lane >> 3) & 1;

    // ---- prologue: Q (own group) + K/V for kt 0,1 ----
    {
#pragma unroll
        for (int i = 0; i < 2; i++) {
            int e = tid + i * 128;
            int r = e >> 1, w = e & 1;
            const __half* src = g_qh + (ull)(b * NN + row0 + r) * CQK + w * 8;
            CP16(smb + QS + r * 32 + w * 16, src);
        }
        CPCOMMIT();
        ISSUE_KV(0, 0);
        ISSUE_KV(1, 1);
    }

    float d0[16][4], d1[16][4];
#pragma unroll
    for (int nb = 0; nb < 16; nb++)
#pragma unroll
        for (int i = 0; i < 4; i++) { d0[nb][i] = 0.0f; d1[nb][i] = 0.0f; }
    float lpA[4] = {0.f, 0.f, 0.f, 0.f};
    float lpB[4] = {0.f, 0.f, 0.f, 0.f};

    u32 qh0[4], qh1[4];
    float cm00, cm01, cm10, cm11;
    {
        CPWAIT2();   // Q group done (KV(0), KV(1) may be outstanding)
        __syncthreads();
        u32 base = QS + (wid * 32 + qr) * 32 + qc * 4;
        qh0[0] = *(const u32*)(sm + base);
        qh0[1] = *(const u32*)(sm + base + 8 * 32);
        qh0[2] = *(const u32*)(sm + base + 16);
        qh0[3] = *(const u32*)(sm + base + 8 * 32 + 16);
        base += 16 * 32;
        qh1[0] = *(const u32*)(sm + base);
        qh1[1] = *(const u32*)(sm + base + 8 * 32);
        qh1[2] = *(const u32*)(sm + base + 16);
        qh1[3] = *(const u32*)(sm + base + 8 * 32 + 16);

        float n00 = nrm2h2(qh0[0]) + nrm2h2(qh0[2]);
        float n01 = nrm2h2(qh0[1]) + nrm2h2(qh0[3]);
        float n10 = nrm2h2(qh1[0]) + nrm2h2(qh1[2]);
        float n11 = nrm2h2(qh1[1]) + nrm2h2(qh1[3]);
        n00 += __shfl_xor_sync(0xffffffffu, n00, 1);
        n00 += __shfl_xor_sync(0xffffffffu, n00, 2);
        n01 += __shfl_xor_sync(0xffffffffu, n01, 1);
        n01 += __shfl_xor_sync(0xffffffffu, n01, 2);
        n10 += __shfl_xor_sync(0xffffffffu, n10, 1);
        n10 += __shfl_xor_sync(0xffffffffu, n10, 2);
        n11 += __shfl_xor_sync(0xffffffffu, n11, 1);
        n11 += __shfl_xor_sync(0xffffffffu, n11, 2);
        cm00 = -(SH_A * sqrtf(n00) + SH_B) * LOG2E;
        cm01 = -(SH_A * sqrtf(n01) + SH_B) * LOG2E;
        cm10 = -(SH_A * sqrtf(n10) + SH_B) * LOG2E;
        cm11 = -(SH_A * sqrtf(n11) + SH_B) * LOG2E;
    }

    // ---- main loop: 2 tiles per barrier ----
    for (int kt2 = 0; kt2 < KT; kt2 += 2) {
        CPWAIT0();          // tiles kt2, kt2+1 landed (all groups complete)
        __syncthreads();    // ... and visible CTA-wide; all warps past kt2-1

        if (kt2 + 2 < KT) ISSUE_KV(kt2 + 2, (kt2 + 2) & 3);
        PROCESS(kt2 & 3);
        if (kt2 + 3 < KT) ISSUE_KV(kt2 + 3, (kt2 + 3) & 3);
        PROCESS((kt2 + 1) & 3);
    }

    // ---- epilogue: normalize (lp exact from ones-MMA), fused residual ----
    const float g = gamma[0];
    const float li00 = g / lpA[0], li01 = g / lpA[2];
    const float li10 = g / lpB[0], li11 = g / lpB[2];

    {
        const int n = row0 + wid * 32 + qr;
#pragma unroll
        for (int nb = 0; nb < 16; nb++) {
            int c = nb * 8 + 2 * qc;
            ull i0 = ((ull)(b * CC + c)) * NN + n;
            out[i0]     = x[i0]     + d0[nb][0] * li00;
            out[i0 + 8] = x[i0 + 8] + d0[nb][2] * li01;
            ull i1 = i0 + NN;
            out[i1]     = x[i1]     + d0[nb][1] * li00;
            out[i1 + 8] = x[i1 + 8] + d0[nb][3] * li01;
            ull j0 = i0 + 16;
            out[j0]     = x[j0]     + d1[nb][0] * li10;
            out[j0 + 8] = x[j0 + 8] + d1[nb][2] * li11;
            ull j1 = j0 + NN;
            out[j1]     = x[j1]     + d1[nb][1] * li10;
            out[j1 + 8] = x[j1 + 8] + d1[nb][3] * li11;
        }
    }
}

// ---------------------------------------------------------------------------
extern "C" void kernel_launch(void* const* d_in, const int* in_sizes, int n_in,
                              void* d_out, int out_size) {
    const float* x     = (const float*)d_in[0];
    const float* Wq    = (const float*)d_in[1];
    const float* Wk    = (const float*)d_in[2];
    const float* Wv    = (const float*)d_in[3];
    const float* gamma = (const float*)d_in[4];
    float* out = (float*)d_out;

    cudaFuncSetAttribute(qkv_kernel,
                         cudaFuncAttributeMaxDynamicSharedMemorySize, QKV_SMEM);
    qkv_kernel<<<dim3(32, 8), 256, QKV_SMEM>>>(x, Wq, Wk, Wv);

    cudaFuncSetAttribute(attn_kernel,
                         cudaFuncAttributeMaxDynamicSharedMemorySize, SMEM_TOTAL);
    attn_kernel<<<dim3(32, 8), 128, SMEM_TOTAL>>>(x, gamma, out);
}